// round 8
// baseline (speedup 1.0000x reference)
#include <cuda_runtime.h>
#include <cuda_fp16.h>
#include <cstdint>

#define NN   100000
#define EE   3200000
#define FIN  256
#define HH   512
#define FOUT 256

#define BM 128
#define BN 128
#define BKH 64               /* K halves per stage (128B rows) */
#define STAGES 3
#define STAGE_BYTES 32768    /* 16KB A + 16KB B */
#define SMEM_BYTES (STAGES * STAGE_BYTES)

#define ACT_SCALE   0.00390625f   /* 2^-8 */
#define ACT_UNSCALE 256.0f

#define SW(o) ((o) ^ (((o) >> 3) & 0x70))

// ---------------- scratch (device globals: no allocation allowed) ----------
__device__ __half g_X0h[(size_t)NN * FIN];
__device__ __half g_X1[(size_t)NN * HH];
__device__ __half g_X2[(size_t)NN * HH];
__device__ __half g_HA[(size_t)NN * HH];
__device__ __half g_HB[(size_t)NN * HH];
__device__ __half g_Z [(size_t)NN * 768];      // layer-4 z0|z1|z2
__device__ float  g_C0[(size_t)NN * HH];       // fp32 partial C (gemmA)
__device__ __half g_B1[512 * 768];             // layer-1 weights [H, 3F]
__device__ __half g_B2[512 * 1536];
__device__ __half g_B3[512 * 1536];
__device__ __half g_B4[768 * 512];             // layer-4 [768, 512]
__device__ int    g_rowptr[NN + 1];
__device__ int    g_cnt[NN];
__device__ int    g_col[EE];
__device__ float  g_wgt[EE];

// ---------------- helpers ---------------------------------------------------
__device__ __forceinline__ uint32_t smem_u32(const void* p) {
    uint32_t a;
    asm("{ .reg .u64 t; cvta.to.shared.u64 t, %1; cvt.u32.u64 %0, t; }" : "=r"(a) : "l"(p));
    return a;
}

template <int N>
__device__ __forceinline__ void cp_wait_group() {
    asm volatile("cp.async.wait_group %0;" :: "n"(N) : "memory");
}

__device__ __forceinline__ void cp16(uint32_t dst, const void* src) {
    asm volatile("cp.async.cg.shared.global [%0], [%1], 16;" :: "r"(dst), "l"(src));
}

__device__ __forceinline__ void ldsm4(uint32_t* r, uint32_t addr) {
    asm volatile("ldmatrix.sync.aligned.m8n8.x4.shared.b16 {%0,%1,%2,%3}, [%4];"
                 : "=r"(r[0]), "=r"(r[1]), "=r"(r[2]), "=r"(r[3]) : "r"(addr));
}

__device__ __forceinline__ void mma_f16(float* c, const uint32_t* a,
                                        uint32_t b0, uint32_t b1) {
    asm volatile(
        "mma.sync.aligned.m16n8k16.row.col.f32.f16.f16.f32 "
        "{%0,%1,%2,%3}, {%4,%5,%6,%7}, {%8,%9}, {%0,%1,%2,%3};"
        : "+f"(c[0]), "+f"(c[1]), "+f"(c[2]), "+f"(c[3])
        : "r"(a[0]), "r"(a[1]), "r"(a[2]), "r"(a[3]), "r"(b0), "r"(b1));
}

__device__ __forceinline__ void acc_edge(float* acc, float wv, uint4 v) {
    float2 f0 = __half22float2(*(__half2*)&v.x);
    float2 f1 = __half22float2(*(__half2*)&v.y);
    float2 f2 = __half22float2(*(__half2*)&v.z);
    float2 f3 = __half22float2(*(__half2*)&v.w);
    acc[0] += wv * f0.x; acc[1] += wv * f0.y;
    acc[2] += wv * f1.x; acc[3] += wv * f1.y;
    acc[4] += wv * f2.x; acc[5] += wv * f2.y;
    acc[6] += wv * f3.x; acc[7] += wv * f3.y;
}

// ---------------- CSR build -------------------------------------------------
__global__ void zero_cnt_kernel() {
    int i = blockIdx.x * blockDim.x + threadIdx.x;
    if (i < NN) g_cnt[i] = 0;
}

__global__ void count_kernel(const int* __restrict__ rows) {
    int i = blockIdx.x * blockDim.x + threadIdx.x;
    if (i < EE) atomicAdd(&g_cnt[rows[i]], 1);
}

__global__ void scan_kernel() {
    __shared__ int s[1024];
    __shared__ int carry;
    int tid = threadIdx.x;
    if (tid == 0) carry = 0;
    __syncthreads();
    for (int base = 0; base < NN; base += 1024) {
        int i = base + tid;
        int v = (i < NN) ? g_cnt[i] : 0;
        s[tid] = v;
        __syncthreads();
        #pragma unroll
        for (int off = 1; off < 1024; off <<= 1) {
            int t = (tid >= off) ? s[tid - off] : 0;
            __syncthreads();
            s[tid] += t;
            __syncthreads();
        }
        int excl = s[tid] - v;
        if (i < NN) {
            int start = carry + excl;
            g_rowptr[i] = start;
            g_cnt[i]    = start;
        }
        __syncthreads();
        if (tid == 1023) carry += s[1023];
        __syncthreads();
    }
    if (tid == 0) g_rowptr[NN] = carry;
}

__global__ void scatter_kernel(const int* __restrict__ rows,
                               const int* __restrict__ cols,
                               const float* __restrict__ w) {
    int i = blockIdx.x * blockDim.x + threadIdx.x;
    if (i < EE) {
        int r = rows[i];
        int p = atomicAdd(&g_cnt[r], 1);
        g_col[p] = cols[i];
        g_wgt[p] = w[i];
    }
}

// ---------------- SpMM: y[r] = alpha * (L x)[r] + beta * s[r] (fp16 io) ----
__global__ __launch_bounds__(128)
void spmm_kernel(const __half* __restrict__ x, int sx,
                 const __half* __restrict__ sub, int ss,
                 __half* __restrict__ y, int sy,
                 float alpha, float beta) {
    __shared__ int   sc[4][32];
    __shared__ float sw[4][32];
    int warp = threadIdx.x >> 5;
    int lane = threadIdx.x & 31;
    int r = blockIdx.x * 4 + warp;
    if (r >= NN) return;
    int beg = g_rowptr[r];
    int end = g_rowptr[r + 1];
    int fo = lane * 8;
    float acc[8] = {0.f, 0.f, 0.f, 0.f, 0.f, 0.f, 0.f, 0.f};
    for (int base = beg; base < end; base += 32) {
        int m = min(32, end - base);
        __syncwarp();
        if (lane < m) { sc[warp][lane] = g_col[base + lane]; sw[warp][lane] = g_wgt[base + lane]; }
        __syncwarp();
        #pragma unroll 4
        for (int j = 0; j < m; j++) {
            uint4 v = *(const uint4*)(x + (size_t)sc[warp][j] * sx + fo);
            acc_edge(acc, sw[warp][j], v);
        }
    }
    float o[8];
    #pragma unroll
    for (int i = 0; i < 8; i++) o[i] = alpha * acc[i];
    if (sub != nullptr) {
        uint4 sv = *(const uint4*)(sub + (size_t)r * ss + fo);
        float2 s0 = __half22float2(*(__half2*)&sv.x);
        float2 s1 = __half22float2(*(__half2*)&sv.y);
        float2 s2 = __half22float2(*(__half2*)&sv.z);
        float2 s3 = __half22float2(*(__half2*)&sv.w);
        o[0] += beta * s0.x; o[1] += beta * s0.y;
        o[2] += beta * s1.x; o[3] += beta * s1.y;
        o[4] += beta * s2.x; o[5] += beta * s2.y;
        o[6] += beta * s3.x; o[7] += beta * s3.y;
    }
    uint4 ov;
    *(__half2*)&ov.x = __floats2half2_rn(o[0], o[1]);
    *(__half2*)&ov.y = __floats2half2_rn(o[2], o[3]);
    *(__half2*)&ov.z = __floats2half2_rn(o[4], o[5]);
    *(__half2*)&ov.w = __floats2half2_rn(o[6], o[7]);
    *(uint4*)(y + (size_t)r * sy + fo) = ov;
}

// ---------------- final SpMM: out = 256*(L v + z0 - z2) + bias (fp32 out) --
__global__ __launch_bounds__(128)
void spmm_final_kernel(const __half* __restrict__ v,
                       const __half* __restrict__ Z,
                       const float* __restrict__ bias,
                       float* __restrict__ out) {
    __shared__ int   sc[4][32];
    __shared__ float sw[4][32];
    int warp = threadIdx.x >> 5;
    int lane = threadIdx.x & 31;
    int r = blockIdx.x * 4 + warp;
    if (r >= NN) return;
    int beg = g_rowptr[r];
    int end = g_rowptr[r + 1];
    int fo = lane * 8;
    float acc[8] = {0.f, 0.f, 0.f, 0.f, 0.f, 0.f, 0.f, 0.f};
    for (int base = beg; base < end; base += 32) {
        int m = min(32, end - base);
        __syncwarp();
        if (lane < m) { sc[warp][lane] = g_col[base + lane]; sw[warp][lane] = g_wgt[base + lane]; }
        __syncwarp();
        #pragma unroll 4
        for (int j = 0; j < m; j++) {
            uint4 vv = *(const uint4*)(v + (size_t)sc[warp][j] * FOUT + fo);
            acc_edge(acc, sw[warp][j], vv);
        }
    }
    uint4 z0v = *(const uint4*)(Z + (size_t)r * 768 + fo);
    uint4 z2v = *(const uint4*)(Z + (size_t)r * 768 + 512 + fo);
    const __half* z0 = (const __half*)&z0v;
    const __half* z2 = (const __half*)&z2v;
    float res[8];
    #pragma unroll
    for (int i = 0; i < 8; i++)
        res[i] = ACT_UNSCALE * (acc[i] + __half2float(z0[i]) - __half2float(z2[i]))
               + bias[fo + i];
    *(float4*)(out + (size_t)r * FOUT + fo)     = make_float4(res[0], res[1], res[2], res[3]);
    *(float4*)(out + (size_t)r * FOUT + fo + 4) = make_float4(res[4], res[5], res[6], res[7]);
}

// ---------------- weight de-interleave --------------------------------------
__global__ void split_kernel(const float* __restrict__ W, __half* __restrict__ B,
                             int F, int Hdim) {
    int idx = blockIdx.x * blockDim.x + threadIdx.x;
    int tot = 3 * F * Hdim;
    if (idx < tot) {
        int kk = idx % (3 * F);
        int o  = idx / (3 * F);
        int seg = kk / F;
        int f   = kk % F;
        B[idx] = __float2half_rn(W[(size_t)o * (3 * F) + f * 3 + seg]);
    }
}

__global__ void split4_kernel(const float* __restrict__ W, __half* __restrict__ B) {
    int idx = blockIdx.x * blockDim.x + threadIdx.x;
    if (idx < 768 * 512) {
        int k = idx % 512;
        int r = idx / 512;
        int seg = r / 256;
        int o   = r % 256;
        B[idx] = __float2half_rn(W[(size_t)o * 1536 + k * 3 + seg]);
    }
}

__global__ void round_kernel(const float* __restrict__ in, __half* __restrict__ out, int n) {
    int i = blockIdx.x * blockDim.x + threadIdx.x;
    if (i < n) out[i] = __float2half_rn(in[i] * ACT_SCALE);
}

// ---------------- mma.sync fp16 GEMM -----------------------------------------
// C = relu?( A@Bt^T + (ADD_C0 ? C0 : bias*bias_scale) )
// A segments [N, F] chosen by kg/F; Bt rows have stride Bstride halves.
__device__ __forceinline__ void load_tile(uint32_t sb, int s, int kt,
                                          const __half* __restrict__ A0,
                                          const __half* __restrict__ A1,
                                          const __half* __restrict__ A2,
                                          const __half* __restrict__ Bt,
                                          int n, int F, int Bstride,
                                          int bm, int bn, int tid) {
    int kg  = kt * BKH;
    int seg = kg / F;
    const __half* Ap = (seg == 0) ? A0 : ((seg == 1) ? A1 : A2);
    int kin = kg - seg * F;
    uint32_t abase = sb + s * STAGE_BYTES;
    uint32_t bbase = abase + 16384;
    #pragma unroll
    for (int i = 0; i < 4; i++) {
        int lin = i * 256 + tid;
        int row = lin >> 3;
        int c16 = lin & 7;
        int gr = bm + row;
        if (gr >= n) gr = n - 1;
        uint32_t off = row * 128 + c16 * 16;
        cp16(abase + SW(off), Ap + (size_t)gr * F + kin + c16 * 8);
    }
    #pragma unroll
    for (int i = 0; i < 4; i++) {
        int lin = i * 256 + tid;
        int row = lin >> 3;
        int c16 = lin & 7;
        uint32_t off = row * 128 + c16 * 16;
        cp16(bbase + SW(off), Bt + (size_t)(bn + row) * Bstride + kg + c16 * 8);
    }
}

template <bool RELU, bool ADD_C0, bool F32OUT>
__global__ __launch_bounds__(256, 2)
void gemm_mma_kernel(const __half* __restrict__ A0,
                     const __half* __restrict__ A1,
                     const __half* __restrict__ A2,
                     const __half* __restrict__ Bt,
                     const float* __restrict__ bias,
                     void* __restrict__ Cv,
                     const float* __restrict__ C0,
                     int n, int F, int Kt, int Bstride, int Hdim,
                     float bias_scale) {
    extern __shared__ char smem[];
    uint32_t sb = smem_u32(smem);
    int tid  = threadIdx.x;
    int lane = tid & 31;
    int wid  = tid >> 5;
    int wm = wid & 1;
    int wn = wid >> 1;
    int bn = blockIdx.x * BN;
    int bm = blockIdx.y * BM;
    int T = Kt / BKH;

    float c[4][4][4];
    #pragma unroll
    for (int mi = 0; mi < 4; mi++)
        #pragma unroll
        for (int j = 0; j < 4; j++)
            #pragma unroll
            for (int e = 0; e < 4; e++) c[mi][j][e] = 0.f;

    #pragma unroll
    for (int p = 0; p < STAGES - 1; p++) {
        load_tile(sb, p, p, A0, A1, A2, Bt, n, F, Bstride, bm, bn, tid);
        asm volatile("cp.async.commit_group;" ::: "memory");
    }

    int lrow16 = lane & 15;
    int lhalf  = (lane >> 4) << 4;

    for (int t = 0; t < T; t++) {
        cp_wait_group<STAGES - 2>();
        __syncthreads();
        int pt = t + STAGES - 1;
        if (pt < T)
            load_tile(sb, pt % STAGES, pt, A0, A1, A2, Bt, n, F, Bstride, bm, bn, tid);
        asm volatile("cp.async.commit_group;" ::: "memory");

        uint32_t abase = sb + (t % STAGES) * STAGE_BYTES;
        uint32_t bbase = abase + 16384;

        #pragma unroll
        for (int ks = 0; ks < 4; ks++) {
            int colb = ks * 32 + lhalf;
            uint32_t a[4][4];
            #pragma unroll
            for (int mi = 0; mi < 4; mi++) {
                uint32_t off = (uint32_t)((wm * 64 + mi * 16 + lrow16) * 128 + colb);
                ldsm4(a[mi], abase + SW(off));
            }
            uint32_t b[2][4];
            #pragma unroll
            for (int p = 0; p < 2; p++) {
                uint32_t off = (uint32_t)((wn * 32 + p * 16 + lrow16) * 128 + colb);
                ldsm4(b[p], bbase + SW(off));
            }
            #pragma unroll
            for (int mi = 0; mi < 4; mi++)
                #pragma unroll
                for (int j = 0; j < 4; j++)
                    mma_f16(c[mi][j], a[mi], b[j >> 1][j & 1], b[j >> 1][2 + (j & 1)]);
        }
    }

    #pragma unroll
    for (int mi = 0; mi < 4; mi++) {
        int r0 = bm + wm * 64 + mi * 16 + (lane >> 2);
        #pragma unroll
        for (int j = 0; j < 4; j++) {
            int col = bn + wn * 32 + j * 8 + (lane & 3) * 2;
            #pragma unroll
            for (int h = 0; h < 2; h++) {
                int r = r0 + h * 8;
                if (r < n) {
                    float v0 = c[mi][j][2 * h];
                    float v1 = c[mi][j][2 * h + 1];
                    if (ADD_C0) {
                        float2 p = *(const float2*)(C0 + (size_t)r * Hdim + col);
                        v0 += p.x; v1 += p.y;
                    } else {
                        v0 += bias[col] * bias_scale;
                        v1 += bias[col + 1] * bias_scale;
                    }
                    if (RELU) { v0 = fmaxf(v0, 0.f); v1 = fmaxf(v1, 0.f); }
                    if (F32OUT) {
                        *(float2*)((float*)Cv + (size_t)r * Hdim + col) = make_float2(v0, v1);
                    } else {
                        __half2* Ch = (__half2*)((__half*)Cv + (size_t)r * Hdim + col);
                        *Ch = __floats2half2_rn(v0, v1);
                    }
                }
            }
        }
    }
}

// ---------------- host orchestration ---------------------------------------
#define SPMM_GRID ((NN + 3) / 4)

struct Ctx {
    cudaStream_t s2;
    cudaEvent_t ev[6];
    Ctx() {
        cudaStreamCreateWithFlags(&s2, cudaStreamNonBlocking);
        for (int i = 0; i < 6; i++)
            cudaEventCreateWithFlags(&ev[i], cudaEventDisableTiming);
    }
};
static Ctx& ctx() { static Ctx c; return c; }

extern "C" void kernel_launch(void* const* d_in, const int* in_sizes, int n_in,
                              void* d_out, int out_size) {
    const float* x    = (const float*)d_in[0];
    const int*   er   = (const int*)d_in[1];
    const int*   ec   = (const int*)d_in[2];
    const float* ew   = (const float*)d_in[3];
    const float* W1   = (const float*)d_in[4];
    const float* b1   = (const float*)d_in[5];
    const float* W2   = (const float*)d_in[6];
    const float* b2   = (const float*)d_in[7];
    const float* W3   = (const float*)d_in[8];
    const float* b3   = (const float*)d_in[9];
    const float* Wout = (const float*)d_in[10];
    const float* bout = (const float*)d_in[11];
    float* out = (float*)d_out;

    __half *X0h, *X1, *X2, *HA, *HB, *B1, *B2, *B3, *B4, *Z;
    float *C0, *dummy_bias;
    cudaGetSymbolAddress((void**)&X0h, g_X0h);
    cudaGetSymbolAddress((void**)&X1,  g_X1);
    cudaGetSymbolAddress((void**)&X2,  g_X2);
    cudaGetSymbolAddress((void**)&HA,  g_HA);
    cudaGetSymbolAddress((void**)&HB,  g_HB);
    cudaGetSymbolAddress((void**)&B1,  g_B1);
    cudaGetSymbolAddress((void**)&B2,  g_B2);
    cudaGetSymbolAddress((void**)&B3,  g_B3);
    cudaGetSymbolAddress((void**)&B4,  g_B4);
    cudaGetSymbolAddress((void**)&Z,   g_Z);
    cudaGetSymbolAddress((void**)&C0,  g_C0);
    cudaGetSymbolAddress((void**)&dummy_bias, g_wgt);

    cudaFuncSetAttribute(gemm_mma_kernel<false, false, true>,
                         cudaFuncAttributeMaxDynamicSharedMemorySize, SMEM_BYTES);
    cudaFuncSetAttribute(gemm_mma_kernel<true, true, false>,
                         cudaFuncAttributeMaxDynamicSharedMemorySize, SMEM_BYTES);
    cudaFuncSetAttribute(gemm_mma_kernel<false, false, false>,
                         cudaFuncAttributeMaxDynamicSharedMemorySize, SMEM_BYTES);

    Ctx& cx = ctx();
    cudaStream_t s2 = cx.s2;
    dim3 gridH(HH / BN, (NN + BM - 1) / BM);
    dim3 grid4(768 / BN, (NN + BM - 1) / BM);

    // ---- fork: side stream does round + all weight splits + gemmA1 ----
    cudaEventRecord(cx.ev[0], 0);
    cudaStreamWaitEvent(s2, cx.ev[0], 0);
    round_kernel<<<(NN * FIN + 255) / 256, 256, 0, s2>>>(x, X0h, NN * FIN);
    split_kernel<<<(3 * FIN * HH + 255) / 256, 256, 0, s2>>>(W1, B1, FIN, HH);
    split_kernel<<<(3 * HH * HH + 255) / 256, 256, 0, s2>>>(W2, B2, HH, HH);
    split_kernel<<<(3 * HH * HH + 255) / 256, 256, 0, s2>>>(W3, B3, HH, HH);
    split4_kernel<<<(768 * 512 + 255) / 256, 256, 0, s2>>>(Wout, B4);
    gemm_mma_kernel<false, false, true><<<gridH, 256, SMEM_BYTES, s2>>>(
        X0h, X0h, X0h, B1, b1, (void*)C0, nullptr, NN, FIN, FIN, 3 * FIN, HH, ACT_SCALE);
    cudaEventRecord(cx.ev[1], s2);

    // ---- main: CSR build (concurrent with side stream) ----
    zero_cnt_kernel<<<(NN + 255) / 256, 256>>>();
    count_kernel<<<(EE + 255) / 256, 256>>>(er);
    scan_kernel<<<1, 1024>>>();
    scatter_kernel<<<(EE + 255) / 256, 256>>>(er, ec, ew);
    cudaStreamWaitEvent(0, cx.ev[1], 0);

    // ---- layer 1: SpMMs + gemmB ----
    spmm_kernel<<<SPMM_GRID, 128>>>(X0h, FIN, nullptr, 0, X1, FIN, 1.f, 0.f);
    spmm_kernel<<<SPMM_GRID, 128>>>(X1, FIN, X0h, FIN, X2, FIN, 2.f, -1.f);
    gemm_mma_kernel<true, true, false><<<gridH, 256, SMEM_BYTES>>>(
        X1, X2, X2, B1 + FIN, b1, HA, C0, NN, FIN, 2 * FIN, 3 * FIN, HH, 0.f);

    // ---- layer 2: fork gemmA2 ----
    cudaEventRecord(cx.ev[2], 0);
    cudaStreamWaitEvent(s2, cx.ev[2], 0);
    gemm_mma_kernel<false, false, true><<<gridH, 256, SMEM_BYTES, s2>>>(
        HA, HA, HA, B2, b2, (void*)C0, nullptr, NN, HH, HH, 3 * HH, HH, ACT_SCALE);
    cudaEventRecord(cx.ev[3], s2);
    for (int c = 0; c < 2; c++) {
        int f0 = c * 256;
        spmm_kernel<<<SPMM_GRID, 128>>>(HA + f0, HH, nullptr, 0, X1 + f0, HH, 1.f, 0.f);
        spmm_kernel<<<SPMM_GRID, 128>>>(X1 + f0, HH, HA + f0, HH, X2 + f0, HH, 2.f, -1.f);
    }
    cudaStreamWaitEvent(0, cx.ev[3], 0);
    gemm_mma_kernel<true, true, false><<<gridH, 256, SMEM_BYTES>>>(
        X1, X2, X2, B2 + HH, b2, HB, C0, NN, HH, 2 * HH, 3 * HH, HH, 0.f);

    // ---- layer 3: fork gemmA3 ----
    cudaEventRecord(cx.ev[4], 0);
    cudaStreamWaitEvent(s2, cx.ev[4], 0);
    gemm_mma_kernel<false, false, true><<<gridH, 256, SMEM_BYTES, s2>>>(
        HB, HB, HB, B3, b3, (void*)C0, nullptr, NN, HH, HH, 3 * HH, HH, ACT_SCALE);
    cudaEventRecord(cx.ev[5], s2);
    for (int c = 0; c < 2; c++) {
        int f0 = c * 256;
        spmm_kernel<<<SPMM_GRID, 128>>>(HB + f0, HH, nullptr, 0, X1 + f0, HH, 1.f, 0.f);
        spmm_kernel<<<SPMM_GRID, 128>>>(X1 + f0, HH, HB + f0, HH, X2 + f0, HH, 2.f, -1.f);
    }
    cudaStreamWaitEvent(0, cx.ev[5], 0);
    gemm_mma_kernel<true, true, false><<<gridH, 256, SMEM_BYTES>>>(
        X1, X2, X2, B3 + HH, b3, HA, C0, NN, HH, 2 * HH, 3 * HH, HH, 0.f);

    // ---- layer 4 (weights-first) ----
    gemm_mma_kernel<false, false, false><<<grid4, 256, SMEM_BYTES>>>(
        HA, HA, HA, B4, dummy_bias, Z, nullptr, NN, HH, HH, HH, 768, 0.f);
    spmm_kernel<<<SPMM_GRID, 128>>>(Z + 512, 768, Z + 256, 768, X1, FOUT, 2.f, 1.f);
    spmm_final_kernel<<<SPMM_GRID, 128>>>(X1, Z, bout, out);
}

// round 9
// speedup vs baseline: 1.5320x; 1.5320x over previous
#include <cuda_runtime.h>
#include <cuda_fp16.h>
#include <cstdint>

#define NN   100000
#define EE   3200000
#define FIN  256
#define HH   512
#define FOUT 256

#define BM 128
#define BN 128
#define BKH 64               /* K halves per stage (128B rows) */
#define STAGES 3
#define STAGE_BYTES 32768    /* 16KB A + 16KB B */
#define SMEM_BYTES (STAGES * STAGE_BYTES)

#define ACT_SCALE   0.00390625f   /* 2^-8 */
#define ACT_UNSCALE 256.0f

#define SW(o) ((o) ^ (((o) >> 3) & 0x70))

// ---------------- scratch (device globals: no allocation allowed) ----------
__device__ __half g_X0h[(size_t)NN * FIN];
__device__ __half g_X1[(size_t)NN * HH];
__device__ __half g_X2[(size_t)NN * HH];
__device__ __half g_HA[(size_t)NN * HH];
__device__ __half g_HB[(size_t)NN * HH];
__device__ __half g_Z [(size_t)NN * 768];      // layer-4 z0|z1|z2
__device__ __half g_B1[512 * 768];             // layer-1 weights [H, 3F]
__device__ __half g_B2[512 * 1536];
__device__ __half g_B3[512 * 1536];
__device__ __half g_B4[768 * 512];             // layer-4 [768, 512]
__device__ int    g_rowptr[NN + 1];
__device__ int    g_cnt[NN];
__device__ int    g_col[EE];
__device__ float  g_wgt[EE];

// ---------------- helpers ---------------------------------------------------
__device__ __forceinline__ uint32_t smem_u32(const void* p) {
    uint32_t a;
    asm("{ .reg .u64 t; cvta.to.shared.u64 t, %1; cvt.u32.u64 %0, t; }" : "=r"(a) : "l"(p));
    return a;
}

template <int N>
__device__ __forceinline__ void cp_wait_group() {
    asm volatile("cp.async.wait_group %0;" :: "n"(N) : "memory");
}

__device__ __forceinline__ void cp16(uint32_t dst, const void* src) {
    asm volatile("cp.async.cg.shared.global [%0], [%1], 16;" :: "r"(dst), "l"(src));
}

__device__ __forceinline__ void ldsm4(uint32_t* r, uint32_t addr) {
    asm volatile("ldmatrix.sync.aligned.m8n8.x4.shared.b16 {%0,%1,%2,%3}, [%4];"
                 : "=r"(r[0]), "=r"(r[1]), "=r"(r[2]), "=r"(r[3]) : "r"(addr));
}

__device__ __forceinline__ void mma_f16(float* c, const uint32_t* a,
                                        uint32_t b0, uint32_t b1) {
    asm volatile(
        "mma.sync.aligned.m16n8k16.row.col.f32.f16.f16.f32 "
        "{%0,%1,%2,%3}, {%4,%5,%6,%7}, {%8,%9}, {%0,%1,%2,%3};"
        : "+f"(c[0]), "+f"(c[1]), "+f"(c[2]), "+f"(c[3])
        : "r"(a[0]), "r"(a[1]), "r"(a[2]), "r"(a[3]), "r"(b0), "r"(b1));
}

__device__ __forceinline__ void acc_edge(float* acc, float wv, uint4 v) {
    float2 f0 = __half22float2(*(__half2*)&v.x);
    float2 f1 = __half22float2(*(__half2*)&v.y);
    float2 f2 = __half22float2(*(__half2*)&v.z);
    float2 f3 = __half22float2(*(__half2*)&v.w);
    acc[0] += wv * f0.x; acc[1] += wv * f0.y;
    acc[2] += wv * f1.x; acc[3] += wv * f1.y;
    acc[4] += wv * f2.x; acc[5] += wv * f2.y;
    acc[6] += wv * f3.x; acc[7] += wv * f3.y;
}

// ---------------- CSR build -------------------------------------------------
__global__ void zero_cnt_kernel() {
    int i = blockIdx.x * blockDim.x + threadIdx.x;
    if (i < NN) g_cnt[i] = 0;
}

__global__ void count_kernel(const int* __restrict__ rows) {
    int i = blockIdx.x * blockDim.x + threadIdx.x;
    if (i < EE) atomicAdd(&g_cnt[rows[i]], 1);
}

__global__ void scan_kernel() {
    __shared__ int s[1024];
    __shared__ int carry;
    int tid = threadIdx.x;
    if (tid == 0) carry = 0;
    __syncthreads();
    for (int base = 0; base < NN; base += 1024) {
        int i = base + tid;
        int v = (i < NN) ? g_cnt[i] : 0;
        s[tid] = v;
        __syncthreads();
        #pragma unroll
        for (int off = 1; off < 1024; off <<= 1) {
            int t = (tid >= off) ? s[tid - off] : 0;
            __syncthreads();
            s[tid] += t;
            __syncthreads();
        }
        int excl = s[tid] - v;
        if (i < NN) {
            int start = carry + excl;
            g_rowptr[i] = start;
            g_cnt[i]    = start;
        }
        __syncthreads();
        if (tid == 1023) carry += s[1023];
        __syncthreads();
    }
    if (tid == 0) g_rowptr[NN] = carry;
}

__global__ void scatter_kernel(const int* __restrict__ rows,
                               const int* __restrict__ cols,
                               const float* __restrict__ w) {
    int i = blockIdx.x * blockDim.x + threadIdx.x;
    if (i < EE) {
        int r = rows[i];
        int p = atomicAdd(&g_cnt[r], 1);
        g_col[p] = cols[i];
        g_wgt[p] = w[i];
    }
}

// ---------------- SpMM: y[r] = alpha * (L x)[r] + beta * s[r] (fp16 io) ----
// 128 threads = 4 warps = 4 rows per block; each lane owns 8 halves (uint4).
__global__ __launch_bounds__(128)
void spmm_kernel(const __half* __restrict__ x, int sx,
                 const __half* __restrict__ sub, int ss,
                 __half* __restrict__ y, int sy,
                 float alpha, float beta) {
    __shared__ int   sc[4][32];
    __shared__ float sw[4][32];
    int warp = threadIdx.x >> 5;
    int lane = threadIdx.x & 31;
    int r = blockIdx.x * 4 + warp;
    if (r >= NN) return;
    int beg = g_rowptr[r];
    int end = g_rowptr[r + 1];
    int fo = lane * 8;
    float acc[8] = {0.f, 0.f, 0.f, 0.f, 0.f, 0.f, 0.f, 0.f};
    for (int base = beg; base < end; base += 32) {
        int m = min(32, end - base);
        __syncwarp();
        if (lane < m) { sc[warp][lane] = g_col[base + lane]; sw[warp][lane] = g_wgt[base + lane]; }
        __syncwarp();
        #pragma unroll 4
        for (int j = 0; j < m; j++) {
            uint4 v = *(const uint4*)(x + (size_t)sc[warp][j] * sx + fo);
            acc_edge(acc, sw[warp][j], v);
        }
    }
    float o[8];
    #pragma unroll
    for (int i = 0; i < 8; i++) o[i] = alpha * acc[i];
    if (sub != nullptr) {
        uint4 sv = *(const uint4*)(sub + (size_t)r * ss + fo);
        float2 s0 = __half22float2(*(__half2*)&sv.x);
        float2 s1 = __half22float2(*(__half2*)&sv.y);
        float2 s2 = __half22float2(*(__half2*)&sv.z);
        float2 s3 = __half22float2(*(__half2*)&sv.w);
        o[0] += beta * s0.x; o[1] += beta * s0.y;
        o[2] += beta * s1.x; o[3] += beta * s1.y;
        o[4] += beta * s2.x; o[5] += beta * s2.y;
        o[6] += beta * s3.x; o[7] += beta * s3.y;
    }
    uint4 ov;
    *(__half2*)&ov.x = __floats2half2_rn(o[0], o[1]);
    *(__half2*)&ov.y = __floats2half2_rn(o[2], o[3]);
    *(__half2*)&ov.z = __floats2half2_rn(o[4], o[5]);
    *(__half2*)&ov.w = __floats2half2_rn(o[6], o[7]);
    *(uint4*)(y + (size_t)r * sy + fo) = ov;
}

// ---------------- final SpMM: out = 256*(L v + z0 - z2) + bias (fp32 out) --
__global__ __launch_bounds__(128)
void spmm_final_kernel(const __half* __restrict__ v,
                       const __half* __restrict__ Z,
                       const float* __restrict__ bias,
                       float* __restrict__ out) {
    __shared__ int   sc[4][32];
    __shared__ float sw[4][32];
    int warp = threadIdx.x >> 5;
    int lane = threadIdx.x & 31;
    int r = blockIdx.x * 4 + warp;
    if (r >= NN) return;
    int beg = g_rowptr[r];
    int end = g_rowptr[r + 1];
    int fo = lane * 8;
    float acc[8] = {0.f, 0.f, 0.f, 0.f, 0.f, 0.f, 0.f, 0.f};
    for (int base = beg; base < end; base += 32) {
        int m = min(32, end - base);
        __syncwarp();
        if (lane < m) { sc[warp][lane] = g_col[base + lane]; sw[warp][lane] = g_wgt[base + lane]; }
        __syncwarp();
        #pragma unroll 4
        for (int j = 0; j < m; j++) {
            uint4 vv = *(const uint4*)(v + (size_t)sc[warp][j] * FOUT + fo);
            acc_edge(acc, sw[warp][j], vv);
        }
    }
    uint4 z0v = *(const uint4*)(Z + (size_t)r * 768 + fo);
    uint4 z2v = *(const uint4*)(Z + (size_t)r * 768 + 512 + fo);
    const __half* z0 = (const __half*)&z0v;
    const __half* z2 = (const __half*)&z2v;
    float res[8];
    #pragma unroll
    for (int i = 0; i < 8; i++)
        res[i] = ACT_UNSCALE * (acc[i] + __half2float(z0[i]) - __half2float(z2[i]))
               + bias[fo + i];
    *(float4*)(out + (size_t)r * FOUT + fo)     = make_float4(res[0], res[1], res[2], res[3]);
    *(float4*)(out + (size_t)r * FOUT + fo + 4) = make_float4(res[4], res[5], res[6], res[7]);
}

// ---------------- weight de-interleave --------------------------------------
__global__ void split_kernel(const float* __restrict__ W, __half* __restrict__ B,
                             int F, int Hdim) {
    int idx = blockIdx.x * blockDim.x + threadIdx.x;
    int tot = 3 * F * Hdim;
    if (idx < tot) {
        int kk = idx % (3 * F);
        int o  = idx / (3 * F);
        int seg = kk / F;
        int f   = kk % F;
        B[idx] = __float2half_rn(W[(size_t)o * (3 * F) + f * 3 + seg]);
    }
}

__global__ void split4_kernel(const float* __restrict__ W, __half* __restrict__ B) {
    int idx = blockIdx.x * blockDim.x + threadIdx.x;
    if (idx < 768 * 512) {
        int k = idx % 512;
        int r = idx / 512;
        int seg = r / 256;
        int o   = r % 256;
        B[idx] = __float2half_rn(W[(size_t)o * 1536 + k * 3 + seg]);
    }
}

__global__ void round_kernel(const float* __restrict__ in, __half* __restrict__ out, int n) {
    int i = blockIdx.x * blockDim.x + threadIdx.x;
    if (i < n) out[i] = __float2half_rn(in[i] * ACT_SCALE);
}

// ---------------- mma.sync fp16 GEMM -----------------------------------------
// C[n, Hdim] = relu?( [A0|A1|A2] @ Bt^T + bias * bias_scale ), fp16/fp32 out.
__device__ __forceinline__ void load_tile(uint32_t sb, int s, int kt,
                                          const __half* __restrict__ A0,
                                          const __half* __restrict__ A1,
                                          const __half* __restrict__ A2,
                                          const __half* __restrict__ Bt,
                                          int n, int F, int Ktot,
                                          int bm, int bn, int tid) {
    int kg  = kt * BKH;
    int seg = kg / F;
    const __half* Ap = (seg == 0) ? A0 : ((seg == 1) ? A1 : A2);
    int kin = kg - seg * F;
    uint32_t abase = sb + s * STAGE_BYTES;
    uint32_t bbase = abase + 16384;
    #pragma unroll
    for (int i = 0; i < 4; i++) {
        int lin = i * 256 + tid;
        int row = lin >> 3;
        int c16 = lin & 7;
        int gr = bm + row;
        if (gr >= n) gr = n - 1;
        uint32_t off = row * 128 + c16 * 16;
        cp16(abase + SW(off), Ap + (size_t)gr * F + kin + c16 * 8);
    }
    #pragma unroll
    for (int i = 0; i < 4; i++) {
        int lin = i * 256 + tid;
        int row = lin >> 3;
        int c16 = lin & 7;
        uint32_t off = row * 128 + c16 * 16;
        cp16(bbase + SW(off), Bt + (size_t)(bn + row) * Ktot + kg + c16 * 8);
    }
}

template <bool RELU>
__global__ __launch_bounds__(256, 2)
void gemm_mma_kernel(const __half* __restrict__ A0,
                     const __half* __restrict__ A1,
                     const __half* __restrict__ A2,
                     const __half* __restrict__ Bt,
                     const float* __restrict__ bias,
                     __half* __restrict__ C,
                     int n, int F, int Ktot, int Hdim,
                     float bias_scale) {
    extern __shared__ char smem[];
    uint32_t sb = smem_u32(smem);
    int tid  = threadIdx.x;
    int lane = tid & 31;
    int wid  = tid >> 5;
    int wm = wid & 1;
    int wn = wid >> 1;
    int bn = blockIdx.x * BN;
    int bm = blockIdx.y * BM;
    int T = Ktot / BKH;

    float c[4][4][4];
    #pragma unroll
    for (int mi = 0; mi < 4; mi++)
        #pragma unroll
        for (int j = 0; j < 4; j++)
            #pragma unroll
            for (int e = 0; e < 4; e++) c[mi][j][e] = 0.f;

    #pragma unroll
    for (int p = 0; p < STAGES - 1; p++) {
        load_tile(sb, p, p, A0, A1, A2, Bt, n, F, Ktot, bm, bn, tid);
        asm volatile("cp.async.commit_group;" ::: "memory");
    }

    int lrow16 = lane & 15;
    int lhalf  = (lane >> 4) << 4;

    for (int t = 0; t < T; t++) {
        cp_wait_group<STAGES - 2>();
        __syncthreads();
        int pt = t + STAGES - 1;
        if (pt < T)
            load_tile(sb, pt % STAGES, pt, A0, A1, A2, Bt, n, F, Ktot, bm, bn, tid);
        asm volatile("cp.async.commit_group;" ::: "memory");

        uint32_t abase = sb + (t % STAGES) * STAGE_BYTES;
        uint32_t bbase = abase + 16384;

        #pragma unroll
        for (int ks = 0; ks < 4; ks++) {
            int colb = ks * 32 + lhalf;
            uint32_t a[4][4];
            #pragma unroll
            for (int mi = 0; mi < 4; mi++) {
                uint32_t off = (uint32_t)((wm * 64 + mi * 16 + lrow16) * 128 + colb);
                ldsm4(a[mi], abase + SW(off));
            }
            uint32_t b[2][4];
            #pragma unroll
            for (int p = 0; p < 2; p++) {
                uint32_t off = (uint32_t)((wn * 32 + p * 16 + lrow16) * 128 + colb);
                ldsm4(b[p], bbase + SW(off));
            }
            #pragma unroll
            for (int mi = 0; mi < 4; mi++)
                #pragma unroll
                for (int j = 0; j < 4; j++)
                    mma_f16(c[mi][j], a[mi], b[j >> 1][j & 1], b[j >> 1][2 + (j & 1)]);
        }
    }

    // epilogue (fp16 out)
    #pragma unroll
    for (int mi = 0; mi < 4; mi++) {
        int r0 = bm + wm * 64 + mi * 16 + (lane >> 2);
        #pragma unroll
        for (int j = 0; j < 4; j++) {
            int col = bn + wn * 32 + j * 8 + (lane & 3) * 2;
            float bb0 = bias[col] * bias_scale;
            float bb1 = bias[col + 1] * bias_scale;
            #pragma unroll
            for (int h = 0; h < 2; h++) {
                int r = r0 + h * 8;
                if (r < n) {
                    float v0 = c[mi][j][2 * h]     + bb0;
                    float v1 = c[mi][j][2 * h + 1] + bb1;
                    if (RELU) { v0 = fmaxf(v0, 0.f); v1 = fmaxf(v1, 0.f); }
                    __half2* Ch = (__half2*)(C + (size_t)r * Hdim + col);
                    *Ch = __floats2half2_rn(v0, v1);
                }
            }
        }
    }
}

// ---------------- host orchestration ---------------------------------------
#define SPMM_GRID ((NN + 3) / 4)

struct Ctx {
    cudaStream_t s2;
    cudaEvent_t ev[2];
    Ctx() {
        cudaStreamCreateWithFlags(&s2, cudaStreamNonBlocking);
        for (int i = 0; i < 2; i++)
            cudaEventCreateWithFlags(&ev[i], cudaEventDisableTiming);
    }
};
static Ctx& ctx() { static Ctx c; return c; }

static void run_hidden_layer(const __half* in, int F,
                             const __half* Bm, const float* bias,
                             __half* X1, __half* X2, __half* outp) {
    for (int c = 0; c < F / 256; c++) {
        int f0 = c * 256;
        spmm_kernel<<<SPMM_GRID, 128>>>(in + f0, F, nullptr, 0, X1 + f0, F, 1.f, 0.f);
        spmm_kernel<<<SPMM_GRID, 128>>>(X1 + f0, F, in + f0, F, X2 + f0, F, 2.f, -1.f);
    }
    dim3 grid(HH / BN, (NN + BM - 1) / BM);
    gemm_mma_kernel<true><<<grid, 256, SMEM_BYTES>>>(
        in, X1, X2, Bm, bias, outp, NN, F, 3 * F, HH, ACT_SCALE);
}

extern "C" void kernel_launch(void* const* d_in, const int* in_sizes, int n_in,
                              void* d_out, int out_size) {
    const float* x    = (const float*)d_in[0];
    const int*   er   = (const int*)d_in[1];
    const int*   ec   = (const int*)d_in[2];
    const float* ew   = (const float*)d_in[3];
    const float* W1   = (const float*)d_in[4];
    const float* b1   = (const float*)d_in[5];
    const float* W2   = (const float*)d_in[6];
    const float* b2   = (const float*)d_in[7];
    const float* W3   = (const float*)d_in[8];
    const float* b3   = (const float*)d_in[9];
    const float* Wout = (const float*)d_in[10];
    const float* bout = (const float*)d_in[11];
    float* out = (float*)d_out;

    __half *X0h, *X1, *X2, *HA, *HB, *B1, *B2, *B3, *B4, *Z;
    float* dummy_bias;
    cudaGetSymbolAddress((void**)&X0h, g_X0h);
    cudaGetSymbolAddress((void**)&X1,  g_X1);
    cudaGetSymbolAddress((void**)&X2,  g_X2);
    cudaGetSymbolAddress((void**)&HA,  g_HA);
    cudaGetSymbolAddress((void**)&HB,  g_HB);
    cudaGetSymbolAddress((void**)&B1,  g_B1);
    cudaGetSymbolAddress((void**)&B2,  g_B2);
    cudaGetSymbolAddress((void**)&B3,  g_B3);
    cudaGetSymbolAddress((void**)&B4,  g_B4);
    cudaGetSymbolAddress((void**)&Z,   g_Z);
    cudaGetSymbolAddress((void**)&dummy_bias, g_wgt);

    cudaFuncSetAttribute(gemm_mma_kernel<true>,
                         cudaFuncAttributeMaxDynamicSharedMemorySize, SMEM_BYTES);
    cudaFuncSetAttribute(gemm_mma_kernel<false>,
                         cudaFuncAttributeMaxDynamicSharedMemorySize, SMEM_BYTES);

    Ctx& cx = ctx();
    cudaStream_t s2 = cx.s2;

    // ---- fork: side stream does round + all weight splits (DRAM-light) ----
    cudaEventRecord(cx.ev[0], 0);
    cudaStreamWaitEvent(s2, cx.ev[0], 0);
    round_kernel<<<(NN * FIN + 255) / 256, 256, 0, s2>>>(x, X0h, NN * FIN);
    split_kernel<<<(3 * FIN * HH + 255) / 256, 256, 0, s2>>>(W1, B1, FIN, HH);
    split_kernel<<<(3 * HH * HH + 255) / 256, 256, 0, s2>>>(W2, B2, HH, HH);
    split_kernel<<<(3 * HH * HH + 255) / 256, 256, 0, s2>>>(W3, B3, HH, HH);
    split4_kernel<<<(768 * 512 + 255) / 256, 256, 0, s2>>>(Wout, B4);
    cudaEventRecord(cx.ev[1], s2);

    // ---- main: CSR build (concurrent) ----
    zero_cnt_kernel<<<(NN + 255) / 256, 256>>>();
    count_kernel<<<(EE + 255) / 256, 256>>>(er);
    scan_kernel<<<1, 1024>>>();
    scatter_kernel<<<(EE + 255) / 256, 256>>>(er, ec, ew);
    cudaStreamWaitEvent(0, cx.ev[1], 0);

    // ---- layers 1-3 ----
    run_hidden_layer(X0h, FIN, B1, b1, X1, X2, HA);
    run_hidden_layer(HA,  HH,  B2, b2, X1, X2, HB);
    run_hidden_layer(HB,  HH,  B3, b3, X1, X2, HA);

    // ---- layer 4 (weights-first) ----
    {
        dim3 grid(768 / BN, (NN + BM - 1) / BM);
        gemm_mma_kernel<false><<<grid, 256, SMEM_BYTES>>>(
            HA, HA, HA, B4, dummy_bias, Z, NN, HH, HH, 768, 0.f);
    }
    spmm_kernel<<<SPMM_GRID, 128>>>(Z + 512, 768, Z + 256, 768, X1, FOUT, 2.f, 1.f);
    spmm_final_kernel<<<SPMM_GRID, 128>>>(X1, Z, bout, out);
}